// round 5
// baseline (speedup 1.0000x reference)
#include <cuda_runtime.h>
#include <math.h>

#define BB 64
#define TT 512
#define II 256
#define HH 512
#define CC 128

#define NBLK 128
#define NTHR 512
#define CHUNK 128
#define INPITCH 132

#define K0 (II + HH)      // 768
#define K1 (HH + HH)      // 1024
#define NWAVE (TT + 1)    // 513

typedef unsigned long long ull;

// ---------------- device scratch ----------------
__device__ float g_h0buf[2][BB * HH];
__device__ float g_h1buf[2][BB * HH];
__device__ float g_h1last[BB * HH];
__device__ unsigned g_ctr;   // zero-init; self-resets at end

// ---------------- primitives ----------------
__device__ __forceinline__ void cp_async16_cg(void* smem_dst, const void* gsrc) {
    unsigned s = (unsigned)__cvta_generic_to_shared(smem_dst);
    asm volatile("cp.async.cg.shared.global [%0], [%1], 16;\n" :: "r"(s), "l"(gsrc) : "memory");
}
__device__ __forceinline__ void cp_commit() {
    asm volatile("cp.async.commit_group;\n" ::: "memory");
}
template <int N>
__device__ __forceinline__ void cp_wait() {
    asm volatile("cp.async.wait_group %0;\n" :: "n"(N) : "memory");
}
__device__ __forceinline__ ull ffma2(ull a, ull b, ull c) {
    ull d;
    asm("fma.rn.f32x2 %0, %1, %2, %3;" : "=l"(d) : "l"(a), "l"(b), "l"(c));
    return d;
}
__device__ __forceinline__ float2 unpack2(ull v) {
    float2 f;
    asm("mov.b64 {%0, %1}, %2;" : "=f"(f.x), "=f"(f.y) : "l"(v));
    return f;
}
__device__ __forceinline__ void bar_arrive(unsigned* ctr, unsigned finalv) {
    unsigned old;
    asm volatile("atom.release.gpu.global.add.u32 %0, [%1], %2;"
                 : "=r"(old) : "l"(ctr), "r"(1u) : "memory");
    if (old == finalv - 1u) {
        asm volatile("st.relaxed.gpu.global.u32 [%0], %1;" :: "l"(ctr), "r"(0u) : "memory");
    }
}
__device__ __forceinline__ void bar_wait(unsigned* ctr, unsigned target) {
    unsigned v;
    do {
        asm volatile("ld.acquire.gpu.global.u32 %0, [%1];" : "=r"(v) : "l"(ctr) : "memory");
    } while (v < target);
}
__device__ __forceinline__ float sigmoidf_(float x) {
    return 1.0f / (1.0f + __expf(-x));
}
__device__ __forceinline__ float tanhf_(float x) {
    return 2.0f / (1.0f + __expf(-2.0f * x)) - 1.0f;
}

// ---------------- inner GEMM chunk: 8 gate rows x 2 batch rows x 16 k per thread --------
template <int KTOT>
__device__ __forceinline__ void compute_chunk(ull* accA, ull* accB,
    const float* __restrict__ ins0, const float* __restrict__ ins1,
    const float* __restrict__ wbase)
{
    #pragma unroll
    for (int k = 0; k < 16; k += 4) {
        ulonglong2 xa = *(const ulonglong2*)(ins0 + k);
        ulonglong2 xb = *(const ulonglong2*)(ins1 + k);
        #pragma unroll
        for (int t4 = 0; t4 < 4; t4++) {
            #pragma unroll
            for (int cc = 0; cc < 2; cc++) {
                ulonglong2 wv = *(const ulonglong2*)(wbase + (t4 * 4 + cc) * KTOT + k);
                int j = t4 * 2 + cc;
                accA[j] = ffma2(xa.x, wv.x, accA[j]);
                accA[j] = ffma2(xa.y, wv.y, accA[j]);
                accB[j] = ffma2(xb.x, wv.x, accB[j]);
                accB[j] = ffma2(xb.y, wv.y, accB[j]);
            }
        }
    }
}

// ---------------- staging: one 64 x 128 chunk of the layer input into smem -------------
__device__ __forceinline__ void stage_chunk(
    float* __restrict__ in_s, const float* __restrict__ xin,
    const float* __restrict__ h0rd, const float* __restrict__ h1rd,
    int tid, int sv, int i)
{
    float* dst = in_s + (i & 1) * (64 * INPITCH);
    const int kbase = (i < 6 ? i : i - 6) * CHUNK;
    #pragma unroll
    for (int q = 0; q < 4; q++) {
        int idx = tid + q * NTHR;
        int row = idx >> 5;
        int k4  = (idx & 31) << 2;
        int kk  = kbase + k4;
        const float* src;
        if (i < 6) {
            src = (kk < II) ? xin + ((size_t)row * TT + sv) * II + kk
                            : h0rd + row * HH + (kk - II);
        } else {
            src = (kk < HH) ? h0rd + row * HH + kk
                            : h1rd + row * HH + (kk - HH);
        }
        cp_async16_cg(dst + row * INPITCH + k4, src);
    }
    cp_commit();
}

// ---------------- epilogue: k-split combine + gates + state update ----------------
__device__ __forceinline__ void epilogue(
    ull* accA, ull* accB, float* pex, const float* bias16,
    int r2, int g2, int ks, int colbase,
    float& cA0, float& cA1, float& cB0, float& cB1,
    float* __restrict__ hout, float* __restrict__ hlast)
{
    float vA[8], vB[8];
    #pragma unroll
    for (int j = 0; j < 8; j++) {
        float2 fa = unpack2(accA[j]); vA[j] = fa.x + fa.y;
        float2 fb = unpack2(accB[j]); vB[j] = fb.x + fb.y;
        accA[j] = 0ull; accB[j] = 0ull;
    }
    int cid = g2 * 32 + r2;
    if (ks) {
        float* d = pex + (ks - 1) * 1024 + cid * 16;
        *(float4*)(d + 0)  = make_float4(vA[0], vA[1], vA[2], vA[3]);
        *(float4*)(d + 4)  = make_float4(vA[4], vA[5], vA[6], vA[7]);
        *(float4*)(d + 8)  = make_float4(vB[0], vB[1], vB[2], vB[3]);
        *(float4*)(d + 12) = make_float4(vB[4], vB[5], vB[6], vB[7]);
    }
    __syncthreads();
    if (!ks) {
        #pragma unroll
        for (int q = 0; q < 7; q++) {
            const float* sp = pex + q * 1024 + cid * 16;
            float4 a0 = *(const float4*)(sp + 0);
            float4 a1 = *(const float4*)(sp + 4);
            float4 b0 = *(const float4*)(sp + 8);
            float4 b1 = *(const float4*)(sp + 12);
            vA[0] += a0.x; vA[1] += a0.y; vA[2] += a0.z; vA[3] += a0.w;
            vA[4] += a1.x; vA[5] += a1.y; vA[6] += a1.z; vA[7] += a1.w;
            vB[0] += b0.x; vB[1] += b0.y; vB[2] += b0.z; vB[3] += b0.w;
            vB[4] += b1.x; vB[5] += b1.y; vB[6] += b1.z; vB[7] += b1.w;
        }
        #pragma unroll
        for (int cc = 0; cc < 2; cc++) {
            float bi = bias16[0 * 4 + 2 * g2 + cc];
            float bf = bias16[1 * 4 + 2 * g2 + cc];
            float bg = bias16[2 * 4 + 2 * g2 + cc];
            float bo = bias16[3 * 4 + 2 * g2 + cc];
            int col = colbase + cc;
            {
                float iv = sigmoidf_(vA[0 + cc] + bi);
                float fv = sigmoidf_(vA[2 + cc] + bf);
                float gv = tanhf_  (vA[4 + cc] + bg);
                float ov = sigmoidf_(vA[6 + cc] + bo);
                float& ca = cc ? cA1 : cA0;
                ca = fv * ca + iv * gv;
                float hv = ov * tanhf_(ca);
                hout[r2 * HH + col] = hv;
                if (hlast) hlast[r2 * HH + col] = hv;
            }
            {
                float iv = sigmoidf_(vB[0 + cc] + bi);
                float fv = sigmoidf_(vB[2 + cc] + bf);
                float gv = tanhf_  (vB[4 + cc] + bg);
                float ov = sigmoidf_(vB[6 + cc] + bo);
                float& cb = cc ? cB1 : cB0;
                cb = fv * cb + iv * gv;
                float hv = ov * tanhf_(cb);
                hout[(r2 + 32) * HH + col] = hv;
                if (hlast) hlast[(r2 + 32) * HH + col] = hv;
            }
        }
    }
    __syncthreads();   // writes visible to tid0 before its release-arrive
}

// ---------------- fused two-layer wavefront LSTM ----------------
__global__ void __launch_bounds__(NTHR, 1) lstm_fused_kernel(
    const float* __restrict__ xin,
    const float* __restrict__ W_ih0, const float* __restrict__ W_hh0,
    const float* __restrict__ b_ih0, const float* __restrict__ b_hh0,
    const float* __restrict__ W_ih1, const float* __restrict__ W_hh1,
    const float* __restrict__ b_ih1, const float* __restrict__ b_hh1,
    const float* __restrict__ h0, const float* __restrict__ c0)
{
    const int tid = threadIdx.x;
    const int blk = blockIdx.x;
    const int r2 = tid & 31;
    const int g2 = (tid >> 5) & 1;
    const int ks = tid >> 6;       // 0..7
    const int koff = ks * 16;
    const int colbase = blk * 4 + g2 * 2;
    const unsigned finalv = (unsigned)NBLK * (NWAVE + 1);

    extern __shared__ float smem[];
    float* W0_s   = smem;                      // [16][768]
    float* W1_s   = W0_s + 16 * K0;            // [16][1024]
    float* in_s   = W1_s + 16 * K1;            // [2][64][132]
    float* pex    = in_s + 2 * 64 * INPITCH;   // [7][1024]
    float* bias_s = pex + 7 * 1024;            // [2][16]

    // --- weights resident in SMEM for both layers ---
    for (int idx = tid; idx < 16 * K0; idx += NTHR) {
        int l = idx / K0, k = idx - l * K0;
        int g = (l >> 2) * HH + blk * 4 + (l & 3);
        W0_s[idx] = (k < II) ? W_ih0[(size_t)g * II + k] : W_hh0[(size_t)g * HH + (k - II)];
    }
    for (int idx = tid; idx < 16 * K1; idx += NTHR) {
        int l = idx / K1, k = idx - l * K1;
        int g = (l >> 2) * HH + blk * 4 + (l & 3);
        W1_s[idx] = (k < HH) ? W_ih1[(size_t)g * HH + k] : W_hh1[(size_t)g * HH + (k - HH)];
    }
    if (tid < 32) {
        int l = tid & 15;
        int g = (l >> 2) * HH + blk * 4 + (l & 3);
        bias_s[tid] = (tid < 16) ? (b_ih0[g] + b_hh0[g]) : (b_ih1[g] + b_hh1[g]);
    }

    if (tid < 256) {
        int i = blk * 256 + tid;
        g_h0buf[0][i] = h0[i];
        g_h1buf[1][i] = h0[BB * HH + i];
    }

    float c0A0 = c0[r2 * HH + colbase],        c0A1 = c0[r2 * HH + colbase + 1];
    float c0B0 = c0[(r2 + 32) * HH + colbase], c0B1 = c0[(r2 + 32) * HH + colbase + 1];
    float c1A0 = c0[BB * HH + r2 * HH + colbase];
    float c1A1 = c0[BB * HH + r2 * HH + colbase + 1];
    float c1B0 = c0[BB * HH + (r2 + 32) * HH + colbase];
    float c1B1 = c0[BB * HH + (r2 + 32) * HH + colbase + 1];

    __syncthreads();
    if (tid == 0) bar_arrive(&g_ctr, finalv);

    ull accA[8] = {0,0,0,0,0,0,0,0};
    ull accB[8] = {0,0,0,0,0,0,0,0};

    // prefetch wave 0, chunk 0 (pure x, no barrier dependency)
    stage_chunk(in_s, xin, nullptr, nullptr, tid, 0, 0);

    #pragma unroll 1
    for (int s = 0; s < NWAVE; s++) {
        const int p = s & 1;
        const float* h0rd = g_h0buf[p];
        const float* h1rd = g_h1buf[p];
        float* h0wr = g_h0buf[p ^ 1];
        float* h1wr = g_h1buf[p ^ 1];
        const unsigned wtarget = (unsigned)(s + 1) * NBLK;
        const int istart = (s == TT) ? 6 : 0;
        const int iend   = (s == 0) ? 6 : 14;

        if (istart == 6) {  // last wave: first chunk reads h, not prefetchable
            if (tid == 0) bar_wait(&g_ctr, wtarget);
            __syncthreads();
            stage_chunk(in_s, xin, h0rd, h1rd, tid, s, 6);
        }

        #pragma unroll 1
        for (int i = istart; i < iend; i++) {
            cp_wait<0>();
            if (i == 1 && tid == 0) bar_wait(&g_ctr, wtarget);  // before first h stage
            __syncthreads();

            if (i + 1 < iend) {
                stage_chunk(in_s, xin, h0rd, h1rd, tid, s, i + 1);
            } else if (s + 1 < TT) {
                stage_chunk(in_s, xin, nullptr, nullptr, tid, s + 1, 0);  // next wave x
            }

            const float* ins0 = in_s + (i & 1) * (64 * INPITCH) + r2 * INPITCH + koff;
            if (i < 6) {
                compute_chunk<K0>(accA, accB, ins0, ins0 + 32 * INPITCH,
                                  W0_s + (2 * g2) * K0 + i * CHUNK + koff);
                if (i == 5)
                    epilogue(accA, accB, pex, bias_s, r2, g2, ks, colbase,
                             c0A0, c0A1, c0B0, c0B1, h0wr, nullptr);
            } else {
                compute_chunk<K1>(accA, accB, ins0, ins0 + 32 * INPITCH,
                                  W1_s + (2 * g2) * K1 + (i - 6) * CHUNK + koff);
                if (i == 13)
                    epilogue(accA, accB, pex, bias_s + 16, r2, g2, ks, colbase,
                             c1A0, c1A1, c1B0, c1B1, h1wr,
                             (s == TT) ? g_h1last : nullptr);
            }
        }
        if (tid == 0) bar_arrive(&g_ctr, finalv);
    }
}

// ---------------- final linear head: one warp per output ----------------
__global__ void fc_kernel(const float* __restrict__ W,   // [C,H]
                          const float* __restrict__ b,   // [C]
                          float* __restrict__ out)       // [B,C]
{
    int w = (blockIdx.x * blockDim.x + threadIdx.x) >> 5;  // 8192 warps
    int lane = threadIdx.x & 31;
    int r = w >> 7;
    int c = w & 127;
    const float* hr = g_h1last + r * HH + lane * 16;
    const float* wc = W + c * HH + lane * 16;
    float acc = 0.0f;
    #pragma unroll
    for (int k = 0; k < 16; k += 4) {
        float4 hv = *(const float4*)(hr + k);
        float4 wv = *(const float4*)(wc + k);
        acc += hv.x * wv.x + hv.y * wv.y + hv.z * wv.z + hv.w * wv.w;
    }
    #pragma unroll
    for (int off = 16; off; off >>= 1) acc += __shfl_xor_sync(~0u, acc, off);
    if (lane == 0) out[w] = acc + b[c];
}

// ---------------- launch ----------------
extern "C" void kernel_launch(void* const* d_in, const int* in_sizes, int n_in,
                              void* d_out, int out_size) {
    const float* x     = (const float*)d_in[0];
    const float* h0    = (const float*)d_in[1];
    const float* c0    = (const float*)d_in[2];
    const float* W_ih0 = (const float*)d_in[3];
    const float* W_hh0 = (const float*)d_in[4];
    const float* b_ih0 = (const float*)d_in[5];
    const float* b_hh0 = (const float*)d_in[6];
    const float* W_ih1 = (const float*)d_in[7];
    const float* W_hh1 = (const float*)d_in[8];
    const float* b_ih1 = (const float*)d_in[9];
    const float* b_hh1 = (const float*)d_in[10];
    const float* W_fc  = (const float*)d_in[11];
    const float* b_fc  = (const float*)d_in[12];

    const int smem_bytes =
        (16 * K0 + 16 * K1 + 2 * 64 * INPITCH + 7 * 1024 + 32) * sizeof(float);
    cudaFuncSetAttribute((const void*)lstm_fused_kernel,
                         cudaFuncAttributeMaxDynamicSharedMemorySize, smem_bytes);

    lstm_fused_kernel<<<NBLK, NTHR, smem_bytes>>>(
        x, W_ih0, W_hh0, b_ih0, b_hh0,
        W_ih1, W_hh1, b_ih1, b_hh1,
        h0, c0);

    fc_kernel<<<(BB * CC * 32) / 256, 256>>>(W_fc, b_fc, (float*)d_out);
}

// round 6
// speedup vs baseline: 1.0025x; 1.0025x over previous
#include <cuda_runtime.h>
#include <math.h>

#define BB 64
#define TT 512
#define II 256
#define HH 512
#define CC 128

#define NBLK 128
#define NTHR 512
#define CHUNK 128
#define INPITCH 132

#define K0 (II + HH)      // 768
#define K1 (HH + HH)      // 1024
#define NWAVE (TT + 1)    // 513

typedef unsigned long long ull;

// ---------------- device scratch ----------------
__device__ float g_h0buf[2][BB * HH];
__device__ float g_h1buf[2][BB * HH];
__device__ float g_h1last[BB * HH];
__device__ unsigned g_ctr;   // zero-init; self-resets at end

// ---------------- primitives ----------------
__device__ __forceinline__ void cp_async16_cg(void* smem_dst, const void* gsrc) {
    unsigned s = (unsigned)__cvta_generic_to_shared(smem_dst);
    asm volatile("cp.async.cg.shared.global [%0], [%1], 16;\n" :: "r"(s), "l"(gsrc) : "memory");
}
__device__ __forceinline__ void cp_commit() {
    asm volatile("cp.async.commit_group;\n" ::: "memory");
}
template <int N>
__device__ __forceinline__ void cp_wait() {
    asm volatile("cp.async.wait_group %0;\n" :: "n"(N) : "memory");
}
__device__ __forceinline__ ull ffma2(ull a, ull b, ull c) {
    ull d;
    asm("fma.rn.f32x2 %0, %1, %2, %3;" : "=l"(d) : "l"(a), "l"(b), "l"(c));
    return d;
}
__device__ __forceinline__ float2 unpack2(ull v) {
    float2 f;
    asm("mov.b64 {%0, %1}, %2;" : "=f"(f.x), "=f"(f.y) : "l"(v));
    return f;
}
__device__ __forceinline__ void bar_arrive(unsigned* ctr, unsigned finalv) {
    unsigned old;
    asm volatile("atom.release.gpu.global.add.u32 %0, [%1], %2;"
                 : "=r"(old) : "l"(ctr), "r"(1u) : "memory");
    if (old == finalv - 1u) {
        asm volatile("st.relaxed.gpu.global.u32 [%0], %1;" :: "l"(ctr), "r"(0u) : "memory");
    }
}
__device__ __forceinline__ void bar_wait(unsigned* ctr, unsigned target) {
    unsigned v;
    do {
        asm volatile("ld.acquire.gpu.global.u32 %0, [%1];" : "=r"(v) : "l"(ctr) : "memory");
    } while (v < target);
}
__device__ __forceinline__ float sigmoidf_(float x) {
    return 1.0f / (1.0f + __expf(-x));
}
__device__ __forceinline__ float tanhf_(float x) {
    return 2.0f / (1.0f + __expf(-2.0f * x)) - 1.0f;
}

// ---------------- inner GEMM chunk: 8 gate rows x 2 batch rows x 16 k per thread --------
template <int KTOT>
__device__ __forceinline__ void compute_chunk(ull* accA, ull* accB,
    const float* __restrict__ ins0, const float* __restrict__ ins1,
    const float* __restrict__ wbase)
{
    #pragma unroll
    for (int k = 0; k < 16; k += 4) {
        ulonglong2 xa = *(const ulonglong2*)(ins0 + k);
        ulonglong2 xb = *(const ulonglong2*)(ins1 + k);
        #pragma unroll
        for (int t4 = 0; t4 < 4; t4++) {
            #pragma unroll
            for (int cc = 0; cc < 2; cc++) {
                ulonglong2 wv = *(const ulonglong2*)(wbase + (t4 * 4 + cc) * KTOT + k);
                int j = t4 * 2 + cc;
                accA[j] = ffma2(xa.x, wv.x, accA[j]);
                accA[j] = ffma2(xa.y, wv.y, accA[j]);
                accB[j] = ffma2(xb.x, wv.x, accB[j]);
                accB[j] = ffma2(xb.y, wv.y, accB[j]);
            }
        }
    }
}

// ---------------- staging: one 64 x 128 chunk of the layer input into smem -------------
__device__ __forceinline__ void stage_chunk(
    float* __restrict__ in_s, const float* __restrict__ xin,
    const float* __restrict__ h0rd, const float* __restrict__ h1rd,
    int tid, int sv, int i)
{
    float* dst = in_s + (i & 1) * (64 * INPITCH);
    const int kbase = (i < 6 ? i : i - 6) * CHUNK;
    #pragma unroll
    for (int q = 0; q < 4; q++) {
        int idx = tid + q * NTHR;
        int row = idx >> 5;
        int k4  = (idx & 31) << 2;
        int kk  = kbase + k4;
        const float* src;
        if (i < 6) {
            src = (kk < II) ? xin + ((size_t)row * TT + sv) * II + kk
                            : h0rd + row * HH + (kk - II);
        } else {
            src = (kk < HH) ? h0rd + row * HH + kk
                            : h1rd + row * HH + (kk - HH);
        }
        cp_async16_cg(dst + row * INPITCH + k4, src);
    }
    cp_commit();
}

// ---------------- epilogue: k-split combine + gates + state update ----------------
__device__ __forceinline__ void epilogue(
    ull* accA, ull* accB, float* pex, const float* bias16,
    int r2, int g2, int ks, int colbase,
    float& cA0, float& cA1, float& cB0, float& cB1,
    float* __restrict__ hout, float* __restrict__ hlast)
{
    float vA[8], vB[8];
    #pragma unroll
    for (int j = 0; j < 8; j++) {
        float2 fa = unpack2(accA[j]); vA[j] = fa.x + fa.y;
        float2 fb = unpack2(accB[j]); vB[j] = fb.x + fb.y;
        accA[j] = 0ull; accB[j] = 0ull;
    }
    int cid = g2 * 32 + r2;
    if (ks) {
        float* d = pex + (ks - 1) * 1024 + cid * 16;
        *(float4*)(d + 0)  = make_float4(vA[0], vA[1], vA[2], vA[3]);
        *(float4*)(d + 4)  = make_float4(vA[4], vA[5], vA[6], vA[7]);
        *(float4*)(d + 8)  = make_float4(vB[0], vB[1], vB[2], vB[3]);
        *(float4*)(d + 12) = make_float4(vB[4], vB[5], vB[6], vB[7]);
    }
    __syncthreads();
    if (!ks) {
        #pragma unroll
        for (int q = 0; q < 7; q++) {
            const float* sp = pex + q * 1024 + cid * 16;
            float4 a0 = *(const float4*)(sp + 0);
            float4 a1 = *(const float4*)(sp + 4);
            float4 b0 = *(const float4*)(sp + 8);
            float4 b1 = *(const float4*)(sp + 12);
            vA[0] += a0.x; vA[1] += a0.y; vA[2] += a0.z; vA[3] += a0.w;
            vA[4] += a1.x; vA[5] += a1.y; vA[6] += a1.z; vA[7] += a1.w;
            vB[0] += b0.x; vB[1] += b0.y; vB[2] += b0.z; vB[3] += b0.w;
            vB[4] += b1.x; vB[5] += b1.y; vB[6] += b1.z; vB[7] += b1.w;
        }
        #pragma unroll
        for (int cc = 0; cc < 2; cc++) {
            float bi = bias16[0 * 4 + 2 * g2 + cc];
            float bf = bias16[1 * 4 + 2 * g2 + cc];
            float bg = bias16[2 * 4 + 2 * g2 + cc];
            float bo = bias16[3 * 4 + 2 * g2 + cc];
            int col = colbase + cc;
            {
                float iv = sigmoidf_(vA[0 + cc] + bi);
                float fv = sigmoidf_(vA[2 + cc] + bf);
                float gv = tanhf_  (vA[4 + cc] + bg);
                float ov = sigmoidf_(vA[6 + cc] + bo);
                float& ca = cc ? cA1 : cA0;
                ca = fv * ca + iv * gv;
                float hv = ov * tanhf_(ca);
                hout[r2 * HH + col] = hv;
                if (hlast) hlast[r2 * HH + col] = hv;
            }
            {
                float iv = sigmoidf_(vB[0 + cc] + bi);
                float fv = sigmoidf_(vB[2 + cc] + bf);
                float gv = tanhf_  (vB[4 + cc] + bg);
                float ov = sigmoidf_(vB[6 + cc] + bo);
                float& cb = cc ? cB1 : cB0;
                cb = fv * cb + iv * gv;
                float hv = ov * tanhf_(cb);
                hout[(r2 + 32) * HH + col] = hv;
                if (hlast) hlast[(r2 + 32) * HH + col] = hv;
            }
        }
    }
    __syncthreads();   // writes visible to tid0 before its release-arrive
}

// ---------------- fused two-layer wavefront LSTM ----------------
__global__ void __launch_bounds__(NTHR, 1) lstm_fused_kernel(
    const float* __restrict__ xin,
    const float* __restrict__ W_ih0, const float* __restrict__ W_hh0,
    const float* __restrict__ b_ih0, const float* __restrict__ b_hh0,
    const float* __restrict__ W_ih1, const float* __restrict__ W_hh1,
    const float* __restrict__ b_ih1, const float* __restrict__ b_hh1,
    const float* __restrict__ h0, const float* __restrict__ c0)
{
    const int tid = threadIdx.x;
    const int blk = blockIdx.x;
    const int r2 = tid & 31;
    const int g2 = (tid >> 5) & 1;
    const int ks = tid >> 6;       // 0..7
    const int koff = ks * 16;
    const int colbase = blk * 4 + g2 * 2;
    const unsigned finalv = (unsigned)NBLK * (NWAVE + 1);

    extern __shared__ float smem[];
    float* W0_s   = smem;                      // [16][768]
    float* W1_s   = W0_s + 16 * K0;            // [16][1024]
    float* in_s   = W1_s + 16 * K1;            // [2][64][132]
    float* pex    = in_s + 2 * 64 * INPITCH;   // [7][1024]
    float* bias_s = pex + 7 * 1024;            // [2][16]

    // --- weights resident in SMEM for both layers ---
    for (int idx = tid; idx < 16 * K0; idx += NTHR) {
        int l = idx / K0, k = idx - l * K0;
        int g = (l >> 2) * HH + blk * 4 + (l & 3);
        W0_s[idx] = (k < II) ? W_ih0[(size_t)g * II + k] : W_hh0[(size_t)g * HH + (k - II)];
    }
    for (int idx = tid; idx < 16 * K1; idx += NTHR) {
        int l = idx / K1, k = idx - l * K1;
        int g = (l >> 2) * HH + blk * 4 + (l & 3);
        W1_s[idx] = (k < HH) ? W_ih1[(size_t)g * HH + k] : W_hh1[(size_t)g * HH + (k - HH)];
    }
    if (tid < 32) {
        int l = tid & 15;
        int g = (l >> 2) * HH + blk * 4 + (l & 3);
        bias_s[tid] = (tid < 16) ? (b_ih0[g] + b_hh0[g]) : (b_ih1[g] + b_hh1[g]);
    }

    if (tid < 256) {
        int i = blk * 256 + tid;
        g_h0buf[0][i] = h0[i];
        g_h1buf[1][i] = h0[BB * HH + i];
    }

    float c0A0 = c0[r2 * HH + colbase],        c0A1 = c0[r2 * HH + colbase + 1];
    float c0B0 = c0[(r2 + 32) * HH + colbase], c0B1 = c0[(r2 + 32) * HH + colbase + 1];
    float c1A0 = c0[BB * HH + r2 * HH + colbase];
    float c1A1 = c0[BB * HH + r2 * HH + colbase + 1];
    float c1B0 = c0[BB * HH + (r2 + 32) * HH + colbase];
    float c1B1 = c0[BB * HH + (r2 + 32) * HH + colbase + 1];

    __syncthreads();
    if (tid == 0) bar_arrive(&g_ctr, finalv);

    ull accA[8] = {0,0,0,0,0,0,0,0};
    ull accB[8] = {0,0,0,0,0,0,0,0};

    // prefetch wave 0, chunk 0 (pure x, no barrier dependency)
    stage_chunk(in_s, xin, nullptr, nullptr, tid, 0, 0);

    #pragma unroll 1
    for (int s = 0; s < NWAVE; s++) {
        const int p = s & 1;
        const float* h0rd = g_h0buf[p];
        const float* h1rd = g_h1buf[p];
        float* h0wr = g_h0buf[p ^ 1];
        float* h1wr = g_h1buf[p ^ 1];
        const unsigned wtarget = (unsigned)(s + 1) * NBLK;
        const int istart = (s == TT) ? 6 : 0;
        const int iend   = (s == 0) ? 6 : 14;

        if (istart == 6) {  // last wave: first chunk reads h, not prefetchable
            if (tid == 0) bar_wait(&g_ctr, wtarget);
            __syncthreads();
            stage_chunk(in_s, xin, h0rd, h1rd, tid, s, 6);
        }

        #pragma unroll 1
        for (int i = istart; i < iend; i++) {
            cp_wait<0>();
            if (i == 1 && tid == 0) bar_wait(&g_ctr, wtarget);  // before first h stage
            __syncthreads();

            if (i + 1 < iend) {
                stage_chunk(in_s, xin, h0rd, h1rd, tid, s, i + 1);
            } else if (s + 1 < TT) {
                stage_chunk(in_s, xin, nullptr, nullptr, tid, s + 1, 0);  // next wave x
            }

            const float* ins0 = in_s + (i & 1) * (64 * INPITCH) + r2 * INPITCH + koff;
            if (i < 6) {
                compute_chunk<K0>(accA, accB, ins0, ins0 + 32 * INPITCH,
                                  W0_s + (2 * g2) * K0 + i * CHUNK + koff);
                if (i == 5)
                    epilogue(accA, accB, pex, bias_s, r2, g2, ks, colbase,
                             c0A0, c0A1, c0B0, c0B1, h0wr, nullptr);
            } else {
                compute_chunk<K1>(accA, accB, ins0, ins0 + 32 * INPITCH,
                                  W1_s + (2 * g2) * K1 + (i - 6) * CHUNK + koff);
                if (i == 13)
                    epilogue(accA, accB, pex, bias_s + 16, r2, g2, ks, colbase,
                             c1A0, c1A1, c1B0, c1B1, h1wr,
                             (s == TT) ? g_h1last : nullptr);
            }
        }
        if (tid == 0) bar_arrive(&g_ctr, finalv);
    }
}

// ---------------- final linear head: one warp per output ----------------
__global__ void fc_kernel(const float* __restrict__ W,   // [C,H]
                          const float* __restrict__ b,   // [C]
                          float* __restrict__ out)       // [B,C]
{
    int w = (blockIdx.x * blockDim.x + threadIdx.x) >> 5;  // 8192 warps
    int lane = threadIdx.x & 31;
    int r = w >> 7;
    int c = w & 127;
    const float* hr = g_h1last + r * HH + lane * 16;
    const float* wc = W + c * HH + lane * 16;
    float acc = 0.0f;
    #pragma unroll
    for (int k = 0; k < 16; k += 4) {
        float4 hv = *(const float4*)(hr + k);
        float4 wv = *(const float4*)(wc + k);
        acc += hv.x * wv.x + hv.y * wv.y + hv.z * wv.z + hv.w * wv.w;
    }
    #pragma unroll
    for (int off = 16; off; off >>= 1) acc += __shfl_xor_sync(~0u, acc, off);
    if (lane == 0) out[w] = acc + b[c];
}

// ---------------- launch ----------------
extern "C" void kernel_launch(void* const* d_in, const int* in_sizes, int n_in,
                              void* d_out, int out_size) {
    const float* x     = (const float*)d_in[0];
    const float* h0    = (const float*)d_in[1];
    const float* c0    = (const float*)d_in[2];
    const float* W_ih0 = (const float*)d_in[3];
    const float* W_hh0 = (const float*)d_in[4];
    const float* b_ih0 = (const float*)d_in[5];
    const float* b_hh0 = (const float*)d_in[6];
    const float* W_ih1 = (const float*)d_in[7];
    const float* W_hh1 = (const float*)d_in[8];
    const float* b_ih1 = (const float*)d_in[9];
    const float* b_hh1 = (const float*)d_in[10];
    const float* W_fc  = (const float*)d_in[11];
    const float* b_fc  = (const float*)d_in[12];

    const int smem_bytes =
        (16 * K0 + 16 * K1 + 2 * 64 * INPITCH + 7 * 1024 + 32) * sizeof(float);
    cudaFuncSetAttribute((const void*)lstm_fused_kernel,
                         cudaFuncAttributeMaxDynamicSharedMemorySize, smem_bytes);

    lstm_fused_kernel<<<NBLK, NTHR, smem_bytes>>>(
        x, W_ih0, W_hh0, b_ih0, b_hh0,
        W_ih1, W_hh1, b_ih1, b_hh1,
        h0, c0);

    fc_kernel<<<(BB * CC * 32) / 256, 256>>>(W_fc, b_fc, (float*)d_out);
}

// round 8
// speedup vs baseline: 1.5274x; 1.5235x over previous
#include <cuda_runtime.h>
#include <cuda_bf16.h>
#include <math.h>

typedef __nv_bfloat16 bf;

#define BB 64
#define TT 512
#define II 256
#define HH 512
#define CC 128

#define NBLK 64
#define NTHR 256
#define NWAVE (TT + 1)   // 513

#define K0 768
#define K1 1024
#define NCH0 12
#define NCH1 16

// smem layout: 3 chunk buffers, each: Whi 8K | Wlo 8K | Xhi 8K | Xlo 8K
#define BUFB 32768
#define SM_EX (3 * BUFB)
#define EXPITCH 66
#define SMEM_TOTAL (SM_EX + 64 * EXPITCH * 4)   // 115200

#define SWZ(o) ((o) ^ (((o) >> 3) & 0x70))

// ---------------- device scratch ----------------
__device__ __align__(256) bf g_w0h[2048 * K0], g_w0l[2048 * K0];
__device__ __align__(256) bf g_w1h[2048 * K1], g_w1l[2048 * K1];
__device__ __align__(256) bf g_xh[(size_t)BB * TT * II], g_xl[(size_t)BB * TT * II];
__device__ __align__(256) bf g_h0h[2][BB * HH], g_h0l[2][BB * HH];
__device__ __align__(256) bf g_h1h[2][BB * HH], g_h1l[2][BB * HH];
__device__ float g_h1last[BB * HH];
__device__ unsigned g_ctr;   // zero-init; self-resets

// ---------------- primitives ----------------
__device__ __forceinline__ void cp16(unsigned saddr, const void* g) {
    asm volatile("cp.async.cg.shared.global [%0], [%1], 16;\n" :: "r"(saddr), "l"(g) : "memory");
}
__device__ __forceinline__ void cp_commit() {
    asm volatile("cp.async.commit_group;\n" ::: "memory");
}
template <int N> __device__ __forceinline__ void cp_wait() {
    asm volatile("cp.async.wait_group %0;\n" :: "n"(N) : "memory");
}
__device__ __forceinline__ void bar_arrive(unsigned* ctr, unsigned finalv) {
    unsigned old;
    asm volatile("atom.release.gpu.global.add.u32 %0, [%1], %2;"
                 : "=r"(old) : "l"(ctr), "r"(1u) : "memory");
    if (old == finalv - 1u)
        asm volatile("st.relaxed.gpu.global.u32 [%0], %1;" :: "l"(ctr), "r"(0u) : "memory");
}
__device__ __forceinline__ void bar_wait(unsigned* ctr, unsigned target) {
    unsigned v;
    do {
        asm volatile("ld.acquire.gpu.global.u32 %0, [%1];" : "=r"(v) : "l"(ctr) : "memory");
    } while (v < target);
}
__device__ __forceinline__ float sig_(float x)  { return 1.0f / (1.0f + __expf(-x)); }
__device__ __forceinline__ float tanh_(float x) { return 2.0f / (1.0f + __expf(-2.0f * x)) - 1.0f; }

__device__ __forceinline__ void ldsm4(unsigned* r, unsigned addr) {
    asm volatile("ldmatrix.sync.aligned.m8n8.x4.shared.b16 {%0,%1,%2,%3}, [%4];"
                 : "=r"(r[0]), "=r"(r[1]), "=r"(r[2]), "=r"(r[3]) : "r"(addr));
}
__device__ __forceinline__ void mma16816(float* c, const unsigned* a, unsigned b0, unsigned b1) {
    asm volatile(
        "mma.sync.aligned.m16n8k16.row.col.f32.bf16.bf16.f32 "
        "{%0,%1,%2,%3}, {%4,%5,%6,%7}, {%8,%9}, {%0,%1,%2,%3};"
        : "+f"(c[0]), "+f"(c[1]), "+f"(c[2]), "+f"(c[3])
        : "r"(a[0]), "r"(a[1]), "r"(a[2]), "r"(a[3]), "r"(b0), "r"(b1));
}

// ---------------- staging: one K=64 chunk (W 64x64 + X 64x64, hi+lo planes) ----------
__device__ __forceinline__ void stage(
    unsigned sbase, unsigned bufoff, int ch, int layer, int sub, int step, int tid, int K,
    const bf* __restrict__ wh, const bf* __restrict__ wl,
    const bf* h0h_, const bf* h0l_, const bf* h1h_, const bf* h1l_)
{
    const unsigned bufa = sbase + bufoff;
    const int kbase = ch * 64;
    #pragma unroll
    for (int q = 0; q < 4; q++) {          // W: 1024 granules
        int idx = tid + q * NTHR;
        int plane = idx >> 9, rem = idx & 511;
        int row = rem >> 3, j = rem & 7;
        const bf* src = (plane ? wl : wh) + (size_t)(sub * 64 + row) * K + kbase + j * 8;
        cp16(bufa + (unsigned)plane * 8192u + SWZ((unsigned)(row * 128 + j * 16)), src);
    }
    #pragma unroll
    for (int q = 0; q < 4; q++) {          // X: 1024 granules
        int idx = tid + q * NTHR;
        int plane = idx >> 9, rem = idx & 511;
        int row = rem >> 3, j = rem & 7;
        int k = kbase + j * 8;
        const bf* src;
        if (layer == 0)
            src = (k < II) ? (plane ? g_xl : g_xh) + ((size_t)row * TT + step) * II + k
                           : (plane ? h0l_ : h0h_) + row * HH + (k - II);
        else
            src = (k < HH) ? (plane ? h0l_ : h0h_) + row * HH + k
                           : (plane ? h1l_ : h1h_) + row * HH + (k - HH);
        cp16(bufa + 16384u + (unsigned)plane * 8192u + SWZ((unsigned)(row * 128 + j * 16)), src);
    }
    cp_commit();
}

// ---------------- tensor compute: one K=64 chunk, 3 bf16 terms ----------------
__device__ __forceinline__ void cchunk(
    unsigned bufa, float acc[4][4],
    unsigned aoff, unsigned boff0, unsigned boff1, unsigned bsel, unsigned msk)
{
    #pragma unroll
    for (int ks = 0; ks < 4; ks++) {
        const unsigned kb = (((unsigned)ks << 5) | bsel) ^ msk;
        unsigned ah[4], al[4], bh[4], bl[4];
        ldsm4(ah, bufa + aoff + kb);               // W hi
        ldsm4(al, bufa + 8192u + aoff + kb);       // W lo
        #pragma unroll
        for (int g = 0; g < 2; g++) {
            const unsigned bo = (g ? boff1 : boff0) + kb;
            ldsm4(bh, bufa + 16384u + bo);         // X hi
            ldsm4(bl, bufa + 24576u + bo);         // X lo
            float* A0 = acc[2 * g];
            float* A1 = acc[2 * g + 1];
            mma16816(A0, ah, bh[0], bh[2]);
            mma16816(A1, ah, bh[1], bh[3]);
            mma16816(A0, ah, bl[0], bl[2]);
            mma16816(A1, ah, bl[1], bl[3]);
            mma16816(A0, al, bh[0], bh[2]);
            mma16816(A1, al, bh[1], bh[3]);
        }
    }
}

// ---------------- main persistent kernel ----------------
__global__ void __launch_bounds__(NTHR, 1) lstm_mma_kernel(
    const float* __restrict__ b_ih0, const float* __restrict__ b_hh0,
    const float* __restrict__ b_ih1, const float* __restrict__ b_hh1,
    const float* __restrict__ h0g, const float* __restrict__ c0g)
{
    extern __shared__ char smem[];
    const unsigned sbase = (unsigned)__cvta_generic_to_shared(smem);
    float* exch = (float*)(smem + SM_EX);

    const int tid = threadIdx.x;
    const int lane = tid & 31, wid = tid >> 5;
    const int blk = blockIdx.x;
    const int layer = blk >> 5, sub = blk & 31;
    const int wm = wid & 3, wn = wid >> 2;
    const unsigned finalv = (unsigned)NBLK * (NWAVE + 1);
    const int K = layer ? K1 : K0;
    const int NCH = layer ? NCH1 : NCH0;
    const bf* wh = layer ? g_w1h : g_w0h;
    const bf* wl = layer ? g_w1l : g_w0l;

    // ldmatrix per-lane constants (SW128: swizzle mask depends only on row%8 = lane%8)
    const unsigned msk  = (unsigned)(lane & 7) << 4;
    const unsigned bsel = (unsigned)(lane & 16);
    const unsigned aoff = (unsigned)((16 * wm + (lane & 15)) * 128);
    const unsigned boff0 = (unsigned)((32 * wn + ((lane >> 3) & 1) * 8 + (lane & 7)) * 128);
    const unsigned boff1 = boff0 + 16 * 128;

    // init h planes (each CTA its own 512-elem slice)
    #pragma unroll
    for (int q = 0; q < 2; q++) {
        int i = blk * 512 + q * 256 + tid;
        float v0 = h0g[i];
        bf a = __float2bfloat16(v0);
        g_h0h[0][i] = a; g_h0l[0][i] = __float2bfloat16(v0 - __bfloat162float(a));
        float v1 = h0g[BB * HH + i];
        bf b = __float2bfloat16(v1);
        g_h1h[1][i] = b; g_h1l[1][i] = __float2bfloat16(v1 - __bfloat162float(b));
    }

    // epilogue role: (h-col, 4 batches) per thread
    const int hc = tid & 15, bg = tid >> 4;
    const int colg = sub * 16 + hc;
    float cst[4];
    #pragma unroll
    for (int q = 0; q < 4; q++)
        cst[q] = c0g[(layer ? BB * HH : 0) + (bg * 4 + q) * HH + colg];
    const float* bih = layer ? b_ih1 : b_ih0;
    const float* bhh = layer ? b_hh1 : b_hh0;
    float bs[4];
    #pragma unroll
    for (int g = 0; g < 4; g++) bs[g] = bih[g * HH + colg] + bhh[g * HH + colg];

    __threadfence();
    __syncthreads();
    if (tid == 0) bar_arrive(&g_ctr, finalv);

    float acc[4][4];
    #pragma unroll
    for (int j = 0; j < 4; j++)
        #pragma unroll
        for (int q = 0; q < 4; q++) acc[j][q] = 0.0f;

    #pragma unroll 1
    for (int s = 0; s < NWAVE; s++) {
        const unsigned wt = (unsigned)(s + 1) * NBLK;
        const bool active = layer ? (s >= 1) : (s < TT);
        if (!active) {
            if (tid == 0) bar_arrive(&g_ctr, finalv);
            continue;
        }
        const int step = layer ? s - 1 : s;
        const int p = s & 1;
        const bf* h0h_ = g_h0h[p]; const bf* h0l_ = g_h0l[p];
        const bf* h1h_ = g_h1h[p]; const bf* h1l_ = g_h1l[p];

        if (layer) {                       // L1: all chunks read prev-wave h
            if (tid == 0) bar_wait(&g_ctr, wt);
            __syncthreads();
        }
        stage(sbase, 0,    0, layer, sub, step, tid, K, wh, wl, h0h_, h0l_, h1h_, h1l_);
        stage(sbase, BUFB, 1, layer, sub, step, tid, K, wh, wl, h0h_, h0l_, h1h_, h1l_);

        #pragma unroll 1
        for (int ch = 0; ch < NCH; ch++) {
            if (ch + 1 < NCH) cp_wait<1>(); else cp_wait<0>();
            __syncthreads();
            if (layer == 0 && ch == 2) {   // before staging chunk 4 (first h chunk)
                if (tid == 0) bar_wait(&g_ctr, wt);
                __syncthreads();
            }
            if (ch + 2 < NCH)
                stage(sbase, (unsigned)((ch + 2) % 3) * BUFB, ch + 2, layer, sub, step, tid,
                      K, wh, wl, h0h_, h0l_, h1h_, h1l_);
            cchunk(sbase + (unsigned)(ch % 3) * BUFB, acc, aoff, boff0, boff1, bsel, msk);
        }

        // ---- epilogue: regs -> smem exchange ----
        {
            const int tq = lane >> 2, tr2 = (lane & 3) * 2;
            #pragma unroll
            for (int j = 0; j < 4; j++) {
                int row = 16 * wm + tq;
                int col = 32 * wn + 8 * j + tr2;
                *(float2*)&exch[row * EXPITCH + col]       = make_float2(acc[j][0], acc[j][1]);
                *(float2*)&exch[(row + 8) * EXPITCH + col] = make_float2(acc[j][2], acc[j][3]);
                acc[j][0] = acc[j][1] = acc[j][2] = acc[j][3] = 0.0f;
            }
        }
        __syncthreads();
        {
            bf* ohh = layer ? g_h1h[p ^ 1] : g_h0h[p ^ 1];
            bf* ohl = layer ? g_h1l[p ^ 1] : g_h0l[p ^ 1];
            #pragma unroll
            for (int q = 0; q < 4; q++) {
                int b = bg * 4 + q;
                float gi = exch[(0  + hc) * EXPITCH + b] + bs[0];
                float gf = exch[(16 + hc) * EXPITCH + b] + bs[1];
                float gg = exch[(32 + hc) * EXPITCH + b] + bs[2];
                float go = exch[(48 + hc) * EXPITCH + b] + bs[3];
                float iv = sig_(gi), fv = sig_(gf), gv = tanh_(gg), ov = sig_(go);
                cst[q] = fv * cst[q] + iv * gv;
                float hv = ov * tanh_(cst[q]);
                bf hhv = __float2bfloat16(hv);
                ohh[b * HH + colg] = hhv;
                ohl[b * HH + colg] = __float2bfloat16(hv - __bfloat162float(hhv));
                if (layer && step == TT - 1) g_h1last[b * HH + colg] = hv;
            }
        }
        __threadfence();
        __syncthreads();
        if (tid == 0) bar_arrive(&g_ctr, finalv);
    }
}

// ---------------- prep kernels ----------------
__global__ void prep_w(const float* __restrict__ Wih, const float* __restrict__ Whh,
                       bf* __restrict__ outh, bf* __restrict__ outl, int Kin, int K) {
    long long idx = (long long)blockIdx.x * blockDim.x + threadIdx.x;
    if (idx >= (long long)2048 * K) return;
    int R = (int)(idx / K), k = (int)(idx - (long long)R * K);
    int sub = R >> 6, l = R & 63;
    int g = (l >> 4) * HH + sub * 16 + (l & 15);
    float v = (k < Kin) ? Wih[(size_t)g * Kin + k] : Whh[(size_t)g * HH + (k - Kin)];
    bf hi = __float2bfloat16(v);
    outh[idx] = hi;
    outl[idx] = __float2bfloat16(v - __bfloat162float(hi));
}
__global__ void prep_x(const float* __restrict__ x) {
    long long idx = (long long)blockIdx.x * blockDim.x + threadIdx.x;
    if (idx >= (long long)BB * TT * II) return;
    float v = x[idx];
    bf hi = __float2bfloat16(v);
    g_xh[idx] = hi;
    g_xl[idx] = __float2bfloat16(v - __bfloat162float(hi));
}

// ---------------- final linear head ----------------
__global__ void fc_kernel(const float* __restrict__ W, const float* __restrict__ b,
                          float* __restrict__ out) {
    int w = (blockIdx.x * blockDim.x + threadIdx.x) >> 5;
    int lane = threadIdx.x & 31;
    int r = w >> 7, c = w & 127;
    const float* hr = g_h1last + r * HH + lane * 16;
    const float* wc = W + c * HH + lane * 16;
    float acc = 0.0f;
    #pragma unroll
    for (int k = 0; k < 16; k += 4) {
        float4 hv = *(const float4*)(hr + k);
        float4 wv = *(const float4*)(wc + k);
        acc += hv.x * wv.x + hv.y * wv.y + hv.z * wv.z + hv.w * wv.w;
    }
    #pragma unroll
    for (int off = 16; off; off >>= 1) acc += __shfl_xor_sync(~0u, acc, off);
    if (lane == 0) out[w] = acc + b[c];
}

// ---------------- launch ----------------
extern "C" void kernel_launch(void* const* d_in, const int* in_sizes, int n_in,
                              void* d_out, int out_size) {
    const float* x     = (const float*)d_in[0];
    const float* h0    = (const float*)d_in[1];
    const float* c0    = (const float*)d_in[2];
    const float* W_ih0 = (const float*)d_in[3];
    const float* W_hh0 = (const float*)d_in[4];
    const float* b_ih0 = (const float*)d_in[5];
    const float* b_hh0 = (const float*)d_in[6];
    const float* W_ih1 = (const float*)d_in[7];
    const float* W_hh1 = (const float*)d_in[8];
    const float* b_ih1 = (const float*)d_in[9];
    const float* b_hh1 = (const float*)d_in[10];
    const float* W_fc  = (const float*)d_in[11];
    const float* b_fc  = (const float*)d_in[12];

    bf *w0h, *w0l, *w1h, *w1l;
    cudaGetSymbolAddress((void**)&w0h, g_w0h);
    cudaGetSymbolAddress((void**)&w0l, g_w0l);
    cudaGetSymbolAddress((void**)&w1h, g_w1h);
    cudaGetSymbolAddress((void**)&w1l, g_w1l);

    prep_w<<<(2048 * K0 + 255) / 256, 256>>>(W_ih0, W_hh0, w0h, w0l, II, K0);
    prep_w<<<(2048 * K1 + 255) / 256, 256>>>(W_ih1, W_hh1, w1h, w1l, HH, K1);
    prep_x<<<(BB * TT * II + 255) / 256, 256>>>(x);

    cudaFuncSetAttribute((const void*)lstm_mma_kernel,
                         cudaFuncAttributeMaxDynamicSharedMemorySize, SMEM_TOTAL);
    lstm_mma_kernel<<<NBLK, NTHR, SMEM_TOTAL>>>(b_ih0, b_hh0, b_ih1, b_hh1, h0, c0);

    fc_kernel<<<(BB * CC * 32) / 256, 256>>>(W_fc, b_fc, (float*)d_out);
}